// round 15
// baseline (speedup 1.0000x reference)
#include <cuda_runtime.h>
#include <cuda_fp16.h>
#include <cstdint>
#include <cstddef>

// Problem constants (fixed by the reference).
#define NN   8192   // N_NODES
#define INF  256    // IN_FEATURES
#define OUTF 32     // OUT_FEATURES

// ---------------------------------------------------------------------------
// Scratch: HW = h @ W in fp16, stored transposed [n][k] with a k-permutation
// within each 16-block so the A operand comes straight from gmem as one
// LDG.128 per lane per (kstep,row):
//   pos(k) = (k&2 ? 8 : 0) + ((k>>2)<<1) + (k&1)
// adj in {0,1} is exact in fp16; fp16 HW gives rel_err ~2e-4 (measured R13).
// ---------------------------------------------------------------------------
__device__ __half g_B[OUTF * NN];            // 512 KB

// ---------------------------------------------------------------------------
// Kernel 1: HW = h @ W (fp32) -> fp16 plane in g_B (permuted k).
// Also zero-inits out. Grid 256 x 256 thr; block = 32 rows; thread = 1 row x
// 4 output features. h staged coalesced in smem (pitch 257, conflict-free);
// W read via L1-broadcast LDG.128.
// ---------------------------------------------------------------------------
__global__ void __launch_bounds__(256) hw_kernel(const float* __restrict__ h,
                                                 const float* __restrict__ W,
                                                 float* __restrict__ out) {
    __shared__ float sh[32 * 257];
    const int t = threadIdx.x;

    // Zero-init out: 65536 threads x 1 float4 = 262144 floats exactly.
    reinterpret_cast<float4*>(out)[blockIdx.x * 256 + t] = make_float4(0.f, 0.f, 0.f, 0.f);

    const int rbase = blockIdx.x * 32;
    for (int i = t; i < 32 * 64; i += 256) {
        const int row = i >> 6, seg = i & 63;
        const float4 v = reinterpret_cast<const float4*>(h + (size_t)(rbase + row) * INF)[seg];
        float* d = &sh[row * 257 + seg * 4];
        d[0] = v.x; d[1] = v.y; d[2] = v.z; d[3] = v.w;
    }
    __syncthreads();

    const int row = t & 31;                 // lane -> row (conflict-free LDS)
    const int n0  = (t >> 5) * 4;           // warp -> 4 output features
    const float* hr = &sh[row * 257];
    float a0 = 0.f, a1 = 0.f, a2 = 0.f, a3 = 0.f;
#pragma unroll 8
    for (int k = 0; k < INF; ++k) {
        const float hv = hr[k];
        const float4 w4 = *reinterpret_cast<const float4*>(W + k * OUTF + n0);  // warp-broadcast
        a0 += hv * w4.x; a1 += hv * w4.y; a2 += hv * w4.z; a3 += hv * w4.w;
    }

    const int grow = rbase + row;
    const int ph   = grow & 15;
    const int p    = ((ph & 2) ? 8 : 0) | ((ph >> 2) << 1) | (ph & 1);
    const int kpos = (grow & ~15) | p;
    g_B[(size_t)(n0 + 0) * NN + kpos] = __float2half_rn(a0);
    g_B[(size_t)(n0 + 1) * NN + kpos] = __float2half_rn(a1);
    g_B[(size_t)(n0 + 2) * NN + kpos] = __float2half_rn(a2);
    g_B[(size_t)(n0 + 3) * NN + kpos] = __float2half_rn(a3);
}

// ---------------------------------------------------------------------------
// Kernel 2: out += adj @ HW via fp16 mma.sync — BARRIER-FREE main loop.
//
// Grid = 2048: 128 m-tiles (BM=64) x 16 K-splits (512 K each).
// CTA = 128 thr = 4 warps; warp w owns rows [w*16,(w+1)*16) x all n=32.
//
// The CTA's ENTIRE B slice (32 n-rows x 512 k = 32 KB) is loaded ONCE into
// smem by a cp.async prologue (single __syncthreads). The 8-chunk main loop
// then has NO barriers, NO smem writes: each warp free-runs on its private
// A register-prefetch stream (2 coalesced LDG.128 per lane per k16, distance
// 1 chunk) against resident B (ldmatrix, pitch 1040 = 16 mod 128 ->
// conflict-free). Latency hiding = many independent warp streams.
// Epilogue: red.global.add.v2.f32 into zero-initialized out.
// ---------------------------------------------------------------------------
#define BK      64
#define BPITCH  1040                   // 512 halfs (1024B) + 16B pad per n-row
#define KSPLIT  16
#define KPER    (NN / KSPLIT)          // 512
#define CH      (KPER / BK)            // 8 chunks per CTA

#define MMA_F16(ACC, A0, A1, A2, A3, B0, B1)                                    \
    asm volatile("mma.sync.aligned.m16n8k16.row.col.f32.f16.f16.f32 "           \
                 "{%0,%1,%2,%3}, {%4,%5,%6,%7}, {%8,%9}, {%0,%1,%2,%3};\n"      \
                 : "+f"((ACC)[0]), "+f"((ACC)[1]), "+f"((ACC)[2]), "+f"((ACC)[3])\
                 : "r"(A0), "r"(A1), "r"(A2), "r"(A3), "r"(B0), "r"(B1))

#define LDMX4(R0, R1, R2, R3, ADDR)                                             \
    asm volatile("ldmatrix.sync.aligned.m8n8.x4.shared.b16 {%0,%1,%2,%3}, [%4];\n"\
                 : "=r"(R0), "=r"(R1), "=r"(R2), "=r"(R3) : "r"(ADDR))

#define REDV2(PTR, X, Y)                                                        \
    asm volatile("red.global.add.v2.f32 [%0], {%1, %2};\n"                      \
                 :: "l"(PTR), "f"(X), "f"(Y) : "memory")

__global__ void __launch_bounds__(128) spmm_kernel(const float* __restrict__ adj,
                                                   float* __restrict__ out) {
    __shared__ __align__(16) char smem[32 * BPITCH];   // 33280 B: whole B slice
    const uint32_t sbB = static_cast<uint32_t>(__cvta_generic_to_shared(smem));

    const int t    = threadIdx.x;
    const int lane = t & 31;
    const int wm   = t >> 5;                    // 4 m-warps
    const int mt   = blockIdx.x & 127;          // m-tile (fast: k-window L2 reuse)
    const int ksid = blockIdx.x >> 7;           // K-split id 0..15
    const int ctaM = mt * 64;
    const int kbase = ksid * KPER;

    // ---- A direct-fragment addressing: lane covers row r=lane/4 (and r+8),
    //      float4 at phys cols 4*(lane%4) within each k16 window.
    const int r  = lane >> 2;
    const int c4 = (lane & 3) << 2;
    const float* aptr = adj + (size_t)(ctaM + wm * 16 + r) * NN + kbase + c4;

    float4 pf[8];                               // prefetch: [kstep]{rows r, r+8}
    auto ld_a = [&](int chunk) {
        const float* p = aptr + chunk * BK;
#pragma unroll
        for (int ks = 0; ks < 4; ++ks) {
            pf[2 * ks]     = *reinterpret_cast<const float4*>(p + ks * 16);
            pf[2 * ks + 1] = *reinterpret_cast<const float4*>(p + ks * 16 + (size_t)8 * NN);
        }
    };

    // ---- Prologue: whole 32 KB B slice via cp.async (one group), and the
    //      first A chunk's LDGs issued BEFORE we wait, both in flight together.
    {
        const __half* s0 = g_B + kbase;
#pragma unroll
        for (int i = 0; i < 16; ++i) {
            const int idx = t + i * 128;        // 2048 x 16B units
            const int row = idx >> 6;           // n-row 0..31
            const int seg = idx & 63;           // 16B segment within 1024B row
            const void* src = s0 + (size_t)row * NN + seg * 8;
            const uint32_t dst = sbB + row * BPITCH + seg * 16;
            asm volatile("cp.async.cg.shared.global [%0], [%1], 16;\n"
                         :: "r"(dst), "l"(src));
        }
        asm volatile("cp.async.commit_group;\n" ::);
    }
    ld_a(0);                                    // overlap with B prologue
    asm volatile("cp.async.wait_group 0;\n" ::);
    __syncthreads();                            // the ONLY barrier

    // ---- B ldmatrix lane offset within a 16-row group.
    const uint32_t brow = (uint32_t)(((lane >> 4) << 3) + (lane & 7));
    const uint32_t bko  = (uint32_t)(((lane >> 3) & 1) << 4);
    const uint32_t boff = brow * BPITCH + bko;

    float acc[4][4] = {};                       // 4 n8-tiles

    for (int chunk = 0; chunk < CH; ++chunk) {
        // Convert prefetched A (frees pf for next chunk's loads).
        uint32_t cur[16];
#pragma unroll
        for (int ks = 0; ks < 4; ++ks) {
            const float4 f = pf[2 * ks], g = pf[2 * ks + 1];
            __half2 q0 = __floats2half2_rn(f.x, f.y);   // a0
            __half2 q1 = __floats2half2_rn(g.x, g.y);   // a1 (r+8)
            __half2 q2 = __floats2half2_rn(f.z, f.w);   // a2
            __half2 q3 = __floats2half2_rn(g.z, g.w);   // a3
            cur[4 * ks + 0] = *reinterpret_cast<uint32_t*>(&q0);
            cur[4 * ks + 1] = *reinterpret_cast<uint32_t*>(&q1);
            cur[4 * ks + 2] = *reinterpret_cast<uint32_t*>(&q2);
            cur[4 * ks + 3] = *reinterpret_cast<uint32_t*>(&q3);
        }
        if (chunk + 1 < CH) ld_a(chunk + 1);    // next chunk's A in flight

        const uint32_t cb = boff + (uint32_t)chunk * 128;   // chunk k-offset
#pragma unroll
        for (int ks = 0; ks < 4; ++ks) {
            uint32_t h0,h1,h2,h3,h4,h5,h6,h7;
            const uint32_t ko = cb + ks * 32;
            LDMX4(h0,h1,h2,h3, sbB + ko);                    // n0-15
            LDMX4(h4,h5,h6,h7, sbB + 16 * BPITCH + ko);      // n16-31
            const uint32_t a0 = cur[4*ks], a1 = cur[4*ks+1],
                           a2 = cur[4*ks+2], a3 = cur[4*ks+3];
            MMA_F16(acc[0], a0,a1,a2,a3, h0,h1);
            MMA_F16(acc[1], a0,a1,a2,a3, h2,h3);
            MMA_F16(acc[2], a0,a1,a2,a3, h4,h5);
            MMA_F16(acc[3], a0,a1,a2,a3, h6,h7);
        }
    }

    // ---- Epilogue: K-split partials via vector reductions (8B-aligned).
    const int row0 = ctaM + wm * 16 + (lane >> 2);
    const int col0 = (lane & 3) * 2;
#pragma unroll
    for (int tile = 0; tile < 4; ++tile) {
        float* o0 = out + (size_t)row0 * OUTF + tile * 8 + col0;
        REDV2(o0,            acc[tile][0], acc[tile][1]);
        REDV2(o0 + 8 * OUTF, acc[tile][2], acc[tile][3]);
    }
}

// ---------------------------------------------------------------------------
// Launch: h [8192*256] f32, adj [8192*8192] f32, W [256*32] f32; out f32.
// Plain launches (PDL regressed under graph capture in R10). Static smem.
// ---------------------------------------------------------------------------
extern "C" void kernel_launch(void* const* d_in, const int* in_sizes, int n_in,
                              void* d_out, int out_size) {
    (void)in_sizes; (void)n_in; (void)out_size;
    const float* h   = reinterpret_cast<const float*>(d_in[0]);
    const float* adj = reinterpret_cast<const float*>(d_in[1]);
    const float* W   = reinterpret_cast<const float*>(d_in[2]);
    float* out       = reinterpret_cast<float*>(d_out);

    hw_kernel<<<NN / 32, 256>>>(h, W, out);                 // HW pack + out=0
    spmm_kernel<<<128 * KSPLIT, 128>>>(adj, out);           // 2048 CTAs
}

// round 17
// speedup vs baseline: 1.1696x; 1.1696x over previous
#include <cuda_runtime.h>
#include <cuda_fp16.h>
#include <cstdint>
#include <cstddef>

// Problem constants (fixed by the reference).
#define NN   8192   // N_NODES
#define INF  256    // IN_FEATURES
#define OUTF 32     // OUT_FEATURES

// ---------------------------------------------------------------------------
// Scratch: HW = h @ W in fp16, stored transposed [n][k] with a k-permutation
// within each 16-block so the A operand comes straight from gmem as one
// LDG.128 per lane per (kstep,row):
//   pos(k) = (k&2 ? 8 : 0) + ((k>>2)<<1) + (k&1)
// adj in {0,1} is exact in fp16; fp16 HW gives rel_err ~2e-4 (measured R13).
// ---------------------------------------------------------------------------
__device__ __half g_B[OUTF * NN];            // 512 KB

// ---------------------------------------------------------------------------
// Kernel 1 (rebuilt for LSU-issue floor): HW = h @ W -> fp16 g_B (permuted k).
// Grid 256 x 256 thr; block = 32 rows. Thread = 2 rows {rp, rp+16} x 4 feats:
// each W fragment (LDG.128, half-warp-uniform) is reused for 2 rows, halving
// W-issue; h is read as LDS.128 over k (pitch 260 words -> conflict-free).
// Per thread: 256 LDG + 128 LDS.128 + 2048 FMA; ~9K cyc/SM ~= 5us.
// Also zero-inits out (256 blocks x 256 thr x float4 = 262144 floats exact).
// ---------------------------------------------------------------------------
#define HPITCH 260                     // words per smem h row (256 + 4 pad)

__global__ void __launch_bounds__(256) hw_kernel(const float* __restrict__ h,
                                                 const float* __restrict__ W,
                                                 float* __restrict__ out) {
    __shared__ __align__(16) float sh[32 * HPITCH];   // 33280 B
    const int t = threadIdx.x;

    // Zero-init out for the atomic epilogue.
    reinterpret_cast<float4*>(out)[blockIdx.x * 256 + t] = make_float4(0.f, 0.f, 0.f, 0.f);

    // Stage h tile [32 x 256] coalesced: 2048 float4, 8 per thread.
    const int rbase = blockIdx.x * 32;
#pragma unroll
    for (int j = 0; j < 8; ++j) {
        const int i = t + j * 256;
        const int row = i >> 6, seg = i & 63;
        const float4 v = reinterpret_cast<const float4*>(h + (size_t)(rbase + row) * INF)[seg];
        *reinterpret_cast<float4*>(&sh[row * HPITCH + seg * 4]) = v;
    }
    __syncthreads();

    const int rp = t & 15;                  // row pair {rp, rp+16}
    const int n0 = (t >> 4) * 4;            // 8 feature groups x 16 row-pairs... wait t>>4 in 0..15
    // t>>4 spans 0..15 but we need 8 groups x 16 pairs = 128 combos per 128
    // threads; with 256 threads each combo is covered twice -> split k range.
    // Simpler: groups = (t >> 4) & 7, khalf = t >> 7 (0/1): each thread does
    // half the k range for its (pair, group); partial sums combined via smem.
    const int grp   = (t >> 4) & 7;
    const int nb    = grp * 4;
    const int khalf = t >> 7;               // 0 or 1: k in [khalf*128, +128)
    const float* hr0 = &sh[rp * HPITCH];
    const float* hr1 = &sh[(rp + 16) * HPITCH];

    float a0[4] = {0.f, 0.f, 0.f, 0.f};     // row rp
    float a1[4] = {0.f, 0.f, 0.f, 0.f};     // row rp+16
    const int k4base = khalf * 32;          // 32 k4-steps each
#pragma unroll 4
    for (int k4 = k4base; k4 < k4base + 32; ++k4) {
        const float4 h0 = *reinterpret_cast<const float4*>(hr0 + k4 * 4);
        const float4 h1 = *reinterpret_cast<const float4*>(hr1 + k4 * 4);
        const float hv0[4] = {h0.x, h0.y, h0.z, h0.w};
        const float hv1[4] = {h1.x, h1.y, h1.z, h1.w};
#pragma unroll
        for (int j = 0; j < 4; ++j) {
            const float4 w4 = *reinterpret_cast<const float4*>(W + (k4 * 4 + j) * OUTF + nb);
            a0[0] += hv0[j] * w4.x; a0[1] += hv0[j] * w4.y;
            a0[2] += hv0[j] * w4.z; a0[3] += hv0[j] * w4.w;
            a1[0] += hv1[j] * w4.x; a1[1] += hv1[j] * w4.y;
            a1[2] += hv1[j] * w4.z; a1[3] += hv1[j] * w4.w;
        }
    }
    __syncthreads();                        // h staging done; reuse smem
    // Combine the two k-halves through smem: khalf 1 publishes, khalf 0 adds.
    float* red = sh;                        // 128 combos x 8 floats = 1024 floats
    if (khalf == 1) {
#pragma unroll
        for (int j = 0; j < 4; ++j) {
            red[(t & 127) * 8 + j]     = a0[j];
            red[(t & 127) * 8 + 4 + j] = a1[j];
        }
    }
    __syncthreads();
    if (khalf == 0) {
#pragma unroll
        for (int j = 0; j < 4; ++j) {
            a0[j] += red[t * 8 + j];
            a1[j] += red[t * 8 + 4 + j];
        }
        // Write fp16 g_B for both rows (permuted k position).
#pragma unroll
        for (int m = 0; m < 2; ++m) {
            const int grow = rbase + rp + m * 16;
            const int ph   = grow & 15;
            const int p    = ((ph & 2) ? 8 : 0) | ((ph >> 2) << 1) | (ph & 1);
            const int kpos = (grow & ~15) | p;
            const float* a = m ? a1 : a0;
#pragma unroll
            for (int j = 0; j < 4; ++j)
                g_B[(size_t)(nb + j) * NN + kpos] = __float2half_rn(a[j]);
        }
    }
}

// ---------------------------------------------------------------------------
// Kernel 2: out += adj_chunk @ HW via fp16 mma.sync — EXACT R13 (proven
// 50.2us: best of 7 structural variants; occupancy/async-depth/barrier-free
// alternatives all measured slower).
//
// Grid = 1024 CTAs: 128 m-tiles (BM=64) x 8 K-splits (1024 K each).
// CTA = 128 threads = 4 warps; warp w owns rows [w*16, w*16+16) x all n=32.
// A: direct gmem fragments (2 coalesced LDG.128 per lane per k16), whole-
//    chunk register prefetch, distance 1.
// B: 4-stage cp.async ring (18.4KB), prefetch depth 3, ONE syncthreads/chunk.
// Epilogue: red.global.add.v2.f32 into zero-initialized out.
// ---------------------------------------------------------------------------
#define BK      64
#define PITCH   144                    // bytes per B smem row (64 halfs + pad)
#define STAGEB  (32 * PITCH)           // 4608 B per stage (32 n-rows)
#define KSPLIT  8
#define KPER    (NN / KSPLIT)          // 1024
#define CH      (KPER / BK)            // 16 chunks per CTA

#define MMA_F16(ACC, A0, A1, A2, A3, B0, B1)                                    \
    asm volatile("mma.sync.aligned.m16n8k16.row.col.f32.f16.f16.f32 "           \
                 "{%0,%1,%2,%3}, {%4,%5,%6,%7}, {%8,%9}, {%0,%1,%2,%3};\n"      \
                 : "+f"((ACC)[0]), "+f"((ACC)[1]), "+f"((ACC)[2]), "+f"((ACC)[3])\
                 : "r"(A0), "r"(A1), "r"(A2), "r"(A3), "r"(B0), "r"(B1))

#define LDMX4(R0, R1, R2, R3, ADDR)                                             \
    asm volatile("ldmatrix.sync.aligned.m8n8.x4.shared.b16 {%0,%1,%2,%3}, [%4];\n"\
                 : "=r"(R0), "=r"(R1), "=r"(R2), "=r"(R3) : "r"(ADDR))

#define REDV2(PTR, X, Y)                                                        \
    asm volatile("red.global.add.v2.f32 [%0], {%1, %2};\n"                      \
                 :: "l"(PTR), "f"(X), "f"(Y) : "memory")

__global__ void __launch_bounds__(128) spmm_kernel(const float* __restrict__ adj,
                                                   float* __restrict__ out) {
    __shared__ __align__(16) char smem[4 * STAGEB];   // 18432 B
    const uint32_t sb0 = static_cast<uint32_t>(__cvta_generic_to_shared(smem));

    const int t    = threadIdx.x;
    const int lane = t & 31;
    const int wm   = t >> 5;                    // 4 m-warps
    const int mt   = blockIdx.x >> 3;           // m-tile 0..127
    const int ksid = blockIdx.x & 7;            // K-split id
    const int ctaM = mt * 64;
    const int kbase = ksid * KPER;

    // ---- A direct-fragment addressing: lane covers row r=lane/4 (and r+8),
    //      float4 at phys cols 4*(lane%4) within each k16 window.
    const int r  = lane >> 2;
    const int c4 = (lane & 3) << 2;
    const float* aptr = adj + (size_t)(ctaM + wm * 16 + r) * NN + kbase + c4;

    float4 pf[8];                               // prefetch: [kstep]{rows r, r+8}
    auto ld_a = [&](int chunk) {
        const float* p = aptr + chunk * BK;
#pragma unroll
        for (int ks = 0; ks < 4; ++ks) {
            pf[2 * ks]     = *reinterpret_cast<const float4*>(p + ks * 16);
            pf[2 * ks + 1] = *reinterpret_cast<const float4*>(p + ks * 16 + (size_t)8 * NN);
        }
    };

    // ---- B cp.async: 32 rows x 128B per chunk; 256 x 16B ops, 2/thread.
    auto cp_b = [&](int chunk) {
        if (chunk < CH) {
            const uint32_t bo = sb0 + (uint32_t)(chunk & 3) * STAGEB;
            const __half* s0 = g_B + kbase + chunk * BK;
#pragma unroll
            for (int i = 0; i < 2; ++i) {
                const int idx = t + i * 128;
                const int row = idx >> 3;       // 0..31 = n
                const int seg = idx & 7;
                const void* src = s0 + (size_t)row * NN + seg * 8;
                const uint32_t dst = bo + row * PITCH + seg * 16;
                asm volatile("cp.async.cg.shared.global [%0], [%1], 16;\n"
                             :: "r"(dst), "l"(src));
            }
        }
        asm volatile("cp.async.commit_group;\n" ::);
    };

    // ---- B ldmatrix lane offset within a 16-row group.
    const uint32_t brow = (uint32_t)(((lane >> 4) << 3) + (lane & 7));
    const uint32_t bko  = (uint32_t)(((lane >> 3) & 1) << 4);
    const uint32_t boff = brow * PITCH + bko;

    float acc[4][4] = {};                       // 4 n8-tiles
    uint32_t cur[16];                           // chunk's packed fp16 A frags

    ld_a(0);
    cp_b(0); cp_b(1); cp_b(2);                  // B prefetch depth 3

    for (int chunk = 0; chunk < CH; ++chunk) {
        // Convert prefetched A (frees pf for next chunk's loads).
#pragma unroll
        for (int ks = 0; ks < 4; ++ks) {
            const float4 f = pf[2 * ks], g = pf[2 * ks + 1];
            __half2 q0 = __floats2half2_rn(f.x, f.y);   // a0
            __half2 q1 = __floats2half2_rn(g.x, g.y);   // a1 (r+8)
            __half2 q2 = __floats2half2_rn(f.z, f.w);   // a2
            __half2 q3 = __floats2half2_rn(g.z, g.w);   // a3
            cur[4 * ks + 0] = *reinterpret_cast<uint32_t*>(&q0);
            cur[4 * ks + 1] = *reinterpret_cast<uint32_t*>(&q1);
            cur[4 * ks + 2] = *reinterpret_cast<uint32_t*>(&q2);
            cur[4 * ks + 3] = *reinterpret_cast<uint32_t*>(&q3);
        }
        if (chunk + 1 < CH) ld_a(chunk + 1);    // next chunk's A in flight

        asm volatile("cp.async.wait_group 2;\n" ::);   // B(chunk) arrived
        __syncthreads();                        // all warps done with chunk-1
        cp_b(chunk + 3);                        // overwrites chunk-1's stage: safe

        const uint32_t sb = sb0 + (uint32_t)(chunk & 3) * STAGEB;
#pragma unroll
        for (int ks = 0; ks < 4; ++ks) {
            uint32_t h0,h1,h2,h3,h4,h5,h6,h7;
            const uint32_t ko = boff + ks * 32;
            LDMX4(h0,h1,h2,h3, sb + ko);                    // n0-15
            LDMX4(h4,h5,h6,h7, sb + 16 * PITCH + ko);       // n16-31
            const uint32_t a0 = cur[4*ks], a1 = cur[4*ks+1],
                           a2 = cur[4*ks+2], a3 = cur[4*ks+3];
            MMA_F16(acc[0], a0,a1,a2,a3, h0,h1);
            MMA_F16(acc[1], a0,a1,a2,a3, h2,h3);
            MMA_F16(acc[2], a0,a1,a2,a3, h4,h5);
            MMA_F16(acc[3], a0,a1,a2,a3, h6,h7);
        }
    }

    // ---- Epilogue: K-split partials via vector reductions (8B-aligned).
    const int row0 = ctaM + wm * 16 + (lane >> 2);
    const int col0 = (lane & 3) * 2;
#pragma unroll
    for (int tile = 0; tile < 4; ++tile) {
        float* o0 = out + (size_t)row0 * OUTF + tile * 8 + col0;
        REDV2(o0,            acc[tile][0], acc[tile][1]);
        REDV2(o0 + 8 * OUTF, acc[tile][2], acc[tile][3]);
    }
}

// ---------------------------------------------------------------------------
// Launch: h [8192*256] f32, adj [8192*8192] f32, W [256*32] f32; out f32.
// Plain launches (PDL regressed under graph capture in R10). Static smem.
// ---------------------------------------------------------------------------
extern "C" void kernel_launch(void* const* d_in, const int* in_sizes, int n_in,
                              void* d_out, int out_size) {
    (void)in_sizes; (void)n_in; (void)out_size;
    const float* h   = reinterpret_cast<const float*>(d_in[0]);
    const float* adj = reinterpret_cast<const float*>(d_in[1]);
    const float* W   = reinterpret_cast<const float*>(d_in[2]);
    float* out       = reinterpret_cast<float*>(d_out);

    hw_kernel<<<NN / 32, 256>>>(h, W, out);                 // HW pack + out=0
    spmm_kernel<<<(NN / 64) * KSPLIT, 128>>>(adj, out);     // 1024 CTAs
}